// round 15
// baseline (speedup 1.0000x reference)
#include <cuda_runtime.h>
#include <cuda_fp16.h>
#include <cstdint>

#define BATCH 32768
#define CHUNK 16384
#define NEMB  20000
#define RPITCH 144                 // bytes per smem row (64 halfs used + pad)
#define A_BYTES (128 * RPITCH)

// ---------------- device scratch (static, allocation-free) ----------------
__device__ __align__(128) __half g_WTh[640 * 256];           // Wq|Wk|Wg|Wo1 rows (fp16)
__device__ __align__(128) __half g_W2h[256 * 256];           // Wo2 (fp16)
__device__ __align__(128) __half g_embh[(size_t)NEMB * 256]; // fp16 embedding copy
__device__ __align__(128) __half g_qh[(size_t)NEMB * 64];    // fp16 q table
__device__ __align__(128) __half g_keh[(size_t)NEMB * 64];   // fp16 ke table
__device__ __align__(128) __half g_gateh[(size_t)NEMB * 256];// fp16 gate table
__device__ __align__(128) float  g_E1c[(size_t)NEMB * 256];  // fp32 E1 + bo + emb table
__device__ __align__(128) __half g_ctxh[(size_t)BATCH * 256];// gated context (fp16)

__device__ __forceinline__ void cp_async16(uint32_t smem_dst, const void* gmem_src) {
    asm volatile("cp.async.cg.shared.global [%0], [%1], 16;\n" :: "r"(smem_dst), "l"(gmem_src));
}
__device__ __forceinline__ void ldsm_x4(uint32_t& r0, uint32_t& r1, uint32_t& r2, uint32_t& r3,
                                        uint32_t saddr) {
    asm volatile("ldmatrix.sync.aligned.m8n8.x4.shared.b16 {%0,%1,%2,%3}, [%4];"
                 : "=r"(r0), "=r"(r1), "=r"(r2), "=r"(r3) : "r"(saddr));
}

// ---------------- K0: fp16 weight assembly + fp16 embedding copy -----------
__global__ void prep_kernel(const float* __restrict__ Wq, const float* __restrict__ Wk,
                            const float* __restrict__ Wg, const float* __restrict__ Wo,
                            const float* __restrict__ embs) {
    int j = blockIdx.x;
    int e = threadIdx.x;
    if (j < 64)        g_WTh[j * 256 + e] = __float2half_rn(Wq[j * 256 + e]);
    else if (j < 128)  g_WTh[j * 256 + e] = __float2half_rn(Wk[(j - 64) * 256 + e]);
    else if (j < 384)  g_WTh[j * 256 + e] = __float2half_rn(Wg[(j - 128) * 256 + e]);
    else if (j < 640)  g_WTh[j * 256 + e] = __float2half_rn(Wo[(j - 384) * 512 + e]);
    else if (j < 896)  g_W2h[(j - 640) * 256 + e] = __float2half_rn(Wo[(j - 640) * 512 + 256 + e]);
    else {
        size_t i = ((size_t)(j - 896) * 256 + e) * 8;
        float4 f0 = *(const float4*)(embs + i);
        float4 f1 = *(const float4*)(embs + i + 4);
        __half2 h[4];
        h[0] = __floats2half2_rn(f0.x, f0.y);
        h[1] = __floats2half2_rn(f0.z, f0.w);
        h[2] = __floats2half2_rn(f1.x, f1.y);
        h[3] = __floats2half2_rn(f1.z, f1.w);
        *(uint4*)(g_embh + i) = *(uint4*)h;
    }
}

// ---------------- GEMM template (fp16 m16n8k16, 2-stage cp.async) ----------
// MODE 0: A = g_embh (contiguous), B = g_WTh slab (nbase selects slabs)
// MODE 1: A = g_ctxh (mbase tiles), B = g_W2h -> + E1c(table), fused LN -> out
template <int MODE, int BROWS, int NTH>
__global__ __launch_bounds__(NTH, (NTH == 512) ? 1 : 2)
void gemm_kernel(const float* __restrict__ all_embs,
                 const int* __restrict__ center_idx,
                 const float* __restrict__ bg,
                 const float* __restrict__ bo,
                 const float* __restrict__ gamma,
                 const float* __restrict__ beta,
                 float* __restrict__ out,
                 int nbase, int mbase) {
    constexpr int STAGE_BYTES = (128 + BROWS) * RPITCH;
    extern __shared__ char sm[];
    __shared__ int   ridx[128];
    __shared__ float redS[128][4];
    __shared__ float redQ[128][4];

    const int t    = threadIdx.x;
    const int lane = t & 31;
    const int warp = t >> 5;
    const int m0 = (mbase + blockIdx.x) * 128;
    const int n0 = (nbase + blockIdx.y) * BROWS;
    const __half* Bmat = (MODE == 0) ? (g_WTh + (size_t)n0 * 256) : g_W2h;

    if (MODE == 1 && t < 128) ridx[t] = center_idx[m0 + t];
    __syncthreads();

    const uint32_t sm_u32 = (uint32_t)__cvta_generic_to_shared(sm);
    const int g   = lane >> 2;
    const int tg  = lane & 3;
    const int mb  = (warp & 3) * 32;
    const int nbo = (warp >> 2) * 64;

    uint32_t a_off[2], b_off[4];
#pragma unroll
    for (int mt = 0; mt < 2; mt++)
        a_off[mt] = (mb + mt * 16 + (lane & 15)) * RPITCH + ((lane >> 4) & 1) * 16;
#pragma unroll
    for (int p = 0; p < 4; p++)
        b_off[p] = A_BYTES + (nbo + p * 16 + ((lane >> 4) & 1) * 8 + (lane & 7)) * RPITCH
                   + ((lane >> 3) & 1) * 16;

    auto load_stage = [&](int kt, int s) {
        const uint32_t dst0 = sm_u32 + s * STAGE_BYTES;
        const int kk = kt * 64;                      // halfs
        for (int idx = t; idx < 128 * 8; idx += NTH) {
            int row = idx >> 3, ch = idx & 7;
            const __half* src;
            if (MODE == 0) {
                int r = m0 + row; if (r >= NEMB) r = NEMB - 1;
                src = g_embh + (size_t)r * 256 + kk + ch * 8;
            } else {
                src = g_ctxh + (size_t)(m0 + row) * 256 + kk + ch * 8;
            }
            cp_async16(dst0 + row * RPITCH + ch * 16, src);
        }
        for (int idx = t; idx < BROWS * 8; idx += NTH) {
            int row = idx >> 3, ch = idx & 7;
            cp_async16(dst0 + A_BYTES + row * RPITCH + ch * 16,
                       Bmat + (size_t)row * 256 + kk + ch * 8);
        }
    };

    float acc[2][8][4] = {};
    uint32_t af[2][2][4];
    uint32_t bf[2][8][2];

    auto load_frags = [&](uint32_t stage, int ks, int buf) {
        const uint32_t kbyte = ks * 32;              // 16 halfs
#pragma unroll
        for (int mt = 0; mt < 2; mt++)
            ldsm_x4(af[buf][mt][0], af[buf][mt][1], af[buf][mt][2], af[buf][mt][3],
                    stage + a_off[mt] + kbyte);
#pragma unroll
        for (int p = 0; p < 4; p++)
            ldsm_x4(bf[buf][2 * p][0], bf[buf][2 * p][1], bf[buf][2 * p + 1][0],
                    bf[buf][2 * p + 1][1], stage + b_off[p] + kbyte);
    };

    load_stage(0, 0);
    asm volatile("cp.async.commit_group;\n" ::: "memory");

#pragma unroll 1
    for (int it = 0; it < 4; ++it) {
        const int s = it & 1;
        asm volatile("cp.async.wait_group 0;\n" ::: "memory");
        __syncthreads();
        if (it + 1 < 4) load_stage(it + 1, s ^ 1);
        asm volatile("cp.async.commit_group;\n" ::: "memory");

        const uint32_t stage = sm_u32 + s * STAGE_BYTES;
        load_frags(stage, 0, 0);
#pragma unroll
        for (int ks = 0; ks < 4; ks++) {
            const int cur = ks & 1;
            if (ks < 3) load_frags(stage, ks + 1, cur ^ 1);
#pragma unroll
            for (int mt = 0; mt < 2; mt++)
#pragma unroll
                for (int nt = 0; nt < 8; nt++)
                    asm volatile(
                        "mma.sync.aligned.m16n8k16.row.col.f32.f16.f16.f32 "
                        "{%0,%1,%2,%3}, {%4,%5,%6,%7}, {%8,%9}, {%0,%1,%2,%3};\n"
                        : "+f"(acc[mt][nt][0]), "+f"(acc[mt][nt][1]),
                          "+f"(acc[mt][nt][2]), "+f"(acc[mt][nt][3])
                        : "r"(af[cur][mt][0]), "r"(af[cur][mt][1]),
                          "r"(af[cur][mt][2]), "r"(af[cur][mt][3]),
                          "r"(bf[cur][nt][0]), "r"(bf[cur][nt][1]));
        }
    }

    if (MODE == 0) {
#pragma unroll
        for (int mt = 0; mt < 2; mt++)
#pragma unroll
            for (int nt = 0; nt < 8; nt++) {
                int j = n0 + nbo + nt * 8 + tg * 2;   // [0,640)
#pragma unroll
                for (int h = 0; h < 2; h++) {
                    int row = m0 + mb + mt * 16 + g + h * 8;
                    if (row >= NEMB) continue;
                    float v0 = acc[mt][nt][h * 2 + 0];
                    float v1 = acc[mt][nt][h * 2 + 1];
                    if (j < 64) {
                        *(__half2*)(g_qh + (size_t)row * 64 + j) = __floats2half2_rn(v0, v1);
                    } else if (j < 128) {
                        *(__half2*)(g_keh + (size_t)row * 64 + (j - 64)) = __floats2half2_rn(v0, v1);
                    } else if (j < 384) {
                        v0 = 1.f / (1.f + __expf(-(v0 + bg[j - 128])));
                        v1 = 1.f / (1.f + __expf(-(v1 + bg[j - 127])));
                        *(__half2*)(g_gateh + (size_t)row * 256 + (j - 128)) = __floats2half2_rn(v0, v1);
                    } else {
                        float2 em = *(const float2*)(all_embs + (size_t)row * 256 + (j - 384));
                        v0 += bo[j - 384] + em.x;
                        v1 += bo[j - 383] + em.y;
                        *(float2*)(g_E1c + (size_t)row * 256 + (j - 384)) = make_float2(v0, v1);
                    }
                }
            }
    } else {
        // MODE 1: + E1c(table), fused LayerNorm
        float rs[4] = {0.f, 0.f, 0.f, 0.f};
        float rq[4] = {0.f, 0.f, 0.f, 0.f};
#pragma unroll
        for (int mt = 0; mt < 2; mt++)
#pragma unroll
            for (int h = 0; h < 2; h++) {
                int lr = mb + mt * 16 + g + h * 8;
                const float* e1r = g_E1c + (size_t)ridx[lr] * 256;
                float s = 0.f, q = 0.f;
#pragma unroll
                for (int nt = 0; nt < 8; nt++) {
                    int j = nbo + nt * 8 + tg * 2;
                    float2 e1 = *(const float2*)(e1r + j);
                    float v0 = acc[mt][nt][h * 2 + 0] + e1.x;
                    float v1 = acc[mt][nt][h * 2 + 1] + e1.y;
                    acc[mt][nt][h * 2 + 0] = v0;
                    acc[mt][nt][h * 2 + 1] = v1;
                    s += v0 + v1;
                    q += v0 * v0 + v1 * v1;
                }
                rs[mt * 2 + h] = s;
                rq[mt * 2 + h] = q;
            }
#pragma unroll
        for (int i = 0; i < 4; i++) {
            rs[i] += __shfl_xor_sync(0xffffffffu, rs[i], 1);
            rs[i] += __shfl_xor_sync(0xffffffffu, rs[i], 2);
            rq[i] += __shfl_xor_sync(0xffffffffu, rq[i], 1);
            rq[i] += __shfl_xor_sync(0xffffffffu, rq[i], 2);
        }
        const int nw = warp >> 2;
        if (tg == 0) {
#pragma unroll
            for (int mt = 0; mt < 2; mt++)
#pragma unroll
                for (int h = 0; h < 2; h++) {
                    int lr = mb + mt * 16 + g + h * 8;
                    redS[lr][nw] = rs[mt * 2 + h];
                    redQ[lr][nw] = rq[mt * 2 + h];
                }
        }
        __syncthreads();
        float mu[4], rstd[4];
#pragma unroll
        for (int mt = 0; mt < 2; mt++)
#pragma unroll
            for (int h = 0; h < 2; h++) {
                int lr = mb + mt * 16 + g + h * 8;
                float s = redS[lr][0] + redS[lr][1] + redS[lr][2] + redS[lr][3];
                float q = redQ[lr][0] + redQ[lr][1] + redQ[lr][2] + redQ[lr][3];
                float m = s * (1.f / 256.f);
                float v = q * (1.f / 256.f) - m * m;
                mu[mt * 2 + h] = m;
                rstd[mt * 2 + h] = rsqrtf(v + 1e-5f);
            }
#pragma unroll
        for (int mt = 0; mt < 2; mt++)
#pragma unroll
            for (int nt = 0; nt < 8; nt++) {
                int j = nbo + nt * 8 + tg * 2;
                float2 gm = *(const float2*)(gamma + j);
                float2 bt = *(const float2*)(beta + j);
#pragma unroll
                for (int h = 0; h < 2; h++) {
                    int row = m0 + mb + mt * 16 + g + h * 8;
                    float m = mu[mt * 2 + h], r = rstd[mt * 2 + h];
                    float o0 = (acc[mt][nt][h * 2 + 0] - m) * r * gm.x + bt.x;
                    float o1 = (acc[mt][nt][h * 2 + 1] - m) * r * gm.y + bt.y;
                    *(float2*)(out + (size_t)row * 256 + j) = make_float2(o0, o1);
                }
            }
    }
}

// ---------------- neigh: group-parallel logits + hfma2 streamed context ----
__global__ __launch_bounds__(256)
void neigh_kernel(const int* __restrict__ center_idx,
                  const int* __restrict__ nb_idx,
                  const float* __restrict__ nb_w,
                  int bbase) {
    const int warp = threadIdx.x >> 5;
    const int lane = threadIdx.x & 31;
    const int b = bbase + blockIdx.x * 8 + warp;
    const int grp = lane >> 3;
    const int u   = lane & 7;

    const int cidx = center_idx[b];

    // q fragment: dims [8u, 8u+8)
    uint4 qv = *(const uint4*)(g_qh + (size_t)cidx * 64 + u * 8);
    const __half2* qh = (const __half2*)&qv;
    float2 qf[4];
#pragma unroll
    for (int i = 0; i < 4; i++) qf[i] = __half22float2(qh[i]);

    int   myidx = 0;
    float myw   = 0.f;
    if (lane < 16) {
        myidx = nb_idx[b * 16 + lane];
        myw   = fmaxf(nb_w[b * 16 + lane], 1e-6f);
    }

    // group-parallel logits (fp32 dot)
    float v[4];
#pragma unroll
    for (int p = 0; p < 4; p++) {
        int r = __shfl_sync(0xffffffffu, myidx, p * 4 + grp);
        uint4 kv = *(const uint4*)(g_keh + (size_t)r * 64 + u * 8);
        const __half2* kh = (const __half2*)&kv;
        float s = 0.f;
#pragma unroll
        for (int i = 0; i < 4; i++) {
            float2 kf = __half22float2(kh[i]);
            s = fmaf(kf.x, qf[i].x, s);
            s = fmaf(kf.y, qf[i].y, s);
        }
        s += __shfl_xor_sync(0xffffffffu, s, 1);
        s += __shfl_xor_sync(0xffffffffu, s, 2);
        s += __shfl_xor_sync(0xffffffffu, s, 4);
        v[p] = s;
    }
    const int src = (lane & 3) * 8;
    float t0 = __shfl_sync(0xffffffffu, v[0], src);
    float t1 = __shfl_sync(0xffffffffu, v[1], src);
    float t2 = __shfl_sync(0xffffffffu, v[2], src);
    float t3 = __shfl_sync(0xffffffffu, v[3], src);
    const int sel = lane >> 2;
    float lgj = (sel == 0) ? t0 : (sel == 1) ? t1 : (sel == 2) ? t2 : t3;

    // softmax over 16 lanes (weights folded: w * exp(l - max))
    float l = (lane < 16) ? lgj * 0.125f : -1e30f;
    float mx = l;
#pragma unroll
    for (int off = 8; off >= 1; off >>= 1)
        mx = fmaxf(mx, __shfl_xor_sync(0xffffffffu, mx, off));
    float e = (lane < 16) ? myw * __expf(l - mx) : 0.f;
    float es = e;
#pragma unroll
    for (int off = 8; off >= 1; off >>= 1)
        es += __shfl_xor_sync(0xffffffffu, es, off);
    float ai = e / es;

    // context: hfma2 accumulation, two sets (even/odd k), fp32 combine.
    __half2 ai2 = __floats2half2_rn(ai, ai);
    uint32_t aiu = *(uint32_t*)&ai2;
    __half2 hacc[2][4];
#pragma unroll
    for (int s2 = 0; s2 < 2; s2++)
#pragma unroll
        for (int i = 0; i < 4; i++) hacc[s2][i] = __floats2half2_rn(0.f, 0.f);

#pragma unroll
    for (int k = 0; k < 16; k++) {
        int      r   = __shfl_sync(0xffffffffu, myidx, k);
        uint32_t aku = __shfl_sync(0xffffffffu, aiu, k);
        __half2  akh = *(__half2*)&aku;
        uint4 nv = *(const uint4*)(g_embh + (size_t)r * 256 + lane * 8);
        const __half2* hp = (const __half2*)&nv;
        const int s2 = k & 1;
#pragma unroll
        for (int i = 0; i < 4; i++)
            hacc[s2][i] = __hfma2(hp[i], akh, hacc[s2][i]);
    }

    float a[8];
#pragma unroll
    for (int i = 0; i < 4; i++) {
        float2 f0 = __half22float2(hacc[0][i]);
        float2 f1 = __half22float2(hacc[1][i]);
        a[2 * i + 0] = f0.x + f1.x;
        a[2 * i + 1] = f0.y + f1.y;
    }

    uint4 gv = *(const uint4*)(g_gateh + (size_t)cidx * 256 + lane * 8);
    const __half2* gh = (const __half2*)&gv;
    __half2 hout[4];
#pragma unroll
    for (int i = 0; i < 4; i++) {
        float2 gf = __half22float2(gh[i]);
        hout[i] = __floats2half2_rn(gf.x * a[2 * i + 0], gf.y * a[2 * i + 1]);
    }
    *(uint4*)(g_ctxh + (size_t)b * 256 + lane * 8) = *(uint4*)hout;
}

// ---------------- launch ---------------------------------------------------
extern "C" void kernel_launch(void* const* d_in, const int* in_sizes, int n_in,
                              void* d_out, int out_size) {
    const float* all_embs   = (const float*)d_in[0];
    const int*   center_idx = (const int*)d_in[1];
    const int*   nb_idx     = (const int*)d_in[2];
    const float* nb_w       = (const float*)d_in[3];
    const float* Wq         = (const float*)d_in[4];
    const float* Wk         = (const float*)d_in[5];
    const float* Wg         = (const float*)d_in[6];
    const float* bg         = (const float*)d_in[7];
    const float* Wo         = (const float*)d_in[8];
    const float* bo         = (const float*)d_in[9];
    const float* gamma      = (const float*)d_in[10];
    const float* beta       = (const float*)d_in[11];
    float* out = (float*)d_out;

    const int sm128 = 2 * (128 + 128) * RPITCH;   // 73728
    const int sm256 = 2 * (128 + 256) * RPITCH;   // 110592

    static cudaStream_t s2 = nullptr, s3 = nullptr;
    static cudaEvent_t ev1 = nullptr, ev2 = nullptr, evA = nullptr, evB = nullptr;
    static int configured = 0;
    if (!configured) {
        cudaFuncSetAttribute((const void*)gemm_kernel<0, 128, 256>,
                             cudaFuncAttributeMaxDynamicSharedMemorySize, sm128);
        cudaFuncSetAttribute((const void*)gemm_kernel<1, 256, 512>,
                             cudaFuncAttributeMaxDynamicSharedMemorySize, sm256);
        cudaStreamCreateWithFlags(&s2, cudaStreamNonBlocking);
        cudaStreamCreateWithFlags(&s3, cudaStreamNonBlocking);
        cudaEventCreateWithFlags(&ev1, cudaEventDisableTiming);
        cudaEventCreateWithFlags(&ev2, cudaEventDisableTiming);
        cudaEventCreateWithFlags(&evA, cudaEventDisableTiming);
        cudaEventCreateWithFlags(&evB, cudaEventDisableTiming);
        configured = 1;
    }

    // s0: prep -> gemm0a(q/ke/gate) -> neigh(c0) -> neigh(c1) -> [join E1c+c0] gemm1(c1)
    // s2: [fork] gemm0b(E1c slabs)
    // s3: [after neigh(c0) + gemm0b] gemm1(c0)   (overlaps neigh(c1))
    prep_kernel<<<896 + 2500, 256>>>(Wq, Wk, Wg, Wo, all_embs);
    cudaEventRecord(ev1, 0);
    cudaStreamWaitEvent(s2, ev1, 0);

    gemm_kernel<0, 128, 256><<<dim3((NEMB + 127) / 128, 3), 256, sm128>>>(
        all_embs, center_idx, bg, bo, gamma, beta, nullptr, 0, 0);    // q|ke|gate
    gemm_kernel<0, 128, 256><<<dim3((NEMB + 127) / 128, 2), 256, sm128, s2>>>(
        all_embs, center_idx, bg, bo, gamma, beta, nullptr, 3, 0);    // E1c (overlapped)
    cudaEventRecord(ev2, s2);

    neigh_kernel<<<CHUNK / 8, 256>>>(center_idx, nb_idx, nb_w, 0);    // chunk 0
    cudaEventRecord(evA, 0);
    cudaStreamWaitEvent(s3, evA, 0);
    cudaStreamWaitEvent(s3, ev2, 0);
    gemm_kernel<1, 256, 512><<<dim3(CHUNK / 128, 1), 512, sm256, s3>>>(
        all_embs, center_idx, bg, bo, gamma, beta, out, 0, 0);        // gemm1 chunk 0

    neigh_kernel<<<CHUNK / 8, 256>>>(center_idx, nb_idx, nb_w, CHUNK);// chunk 1 (overlaps)
    cudaStreamWaitEvent(0, ev2, 0);
    gemm_kernel<1, 256, 512><<<dim3(CHUNK / 128, 1), 512, sm256>>>(
        all_embs, center_idx, bg, bo, gamma, beta, out, 0, CHUNK / 128); // gemm1 chunk 1

    cudaEventRecord(evB, s3);
    cudaStreamWaitEvent(0, evB, 0);                                   // join
}

// round 16
// speedup vs baseline: 1.0223x; 1.0223x over previous
#include <cuda_runtime.h>
#include <cuda_fp16.h>
#include <cstdint>

#define BATCH 32768
#define NEMB  20000
#define RPITCH 144                 // bytes per smem row (64 halfs used + pad)

// ---------------- device scratch (static, allocation-free) ----------------
__device__ __align__(128) __half g_WTh[640 * 256];           // Wq|Wk|Wg|Wo1 rows (fp16)
__device__ __align__(128) __half g_W2h[256 * 256];           // Wo2 (fp16)
__device__ __align__(128) __half g_embh[(size_t)NEMB * 256]; // fp16 embedding copy
__device__ __align__(128) __half g_qh[(size_t)NEMB * 64];    // fp16 q table
__device__ __align__(128) __half g_keh[(size_t)NEMB * 64];   // fp16 ke table
__device__ __align__(128) __half g_gateh[(size_t)NEMB * 256];// fp16 gate table
__device__ __align__(128) float  g_E1c[(size_t)NEMB * 256];  // fp32 E1 + bo + emb table
__device__ __align__(128) __half g_ctxh[(size_t)BATCH * 256];// gated context (fp16)

__device__ __forceinline__ void cp_async16(uint32_t smem_dst, const void* gmem_src) {
    asm volatile("cp.async.cg.shared.global [%0], [%1], 16;\n" :: "r"(smem_dst), "l"(gmem_src));
}
__device__ __forceinline__ void ldsm_x4(uint32_t& r0, uint32_t& r1, uint32_t& r2, uint32_t& r3,
                                        uint32_t saddr) {
    asm volatile("ldmatrix.sync.aligned.m8n8.x4.shared.b16 {%0,%1,%2,%3}, [%4];"
                 : "=r"(r0), "=r"(r1), "=r"(r2), "=r"(r3) : "r"(saddr));
}

// ---------------- K0: fp16 weight assembly + fp16 embedding copy -----------
__global__ void prep_kernel(const float* __restrict__ Wq, const float* __restrict__ Wk,
                            const float* __restrict__ Wg, const float* __restrict__ Wo,
                            const float* __restrict__ embs) {
    int j = blockIdx.x;
    int e = threadIdx.x;
    if (j < 64)        g_WTh[j * 256 + e] = __float2half_rn(Wq[j * 256 + e]);
    else if (j < 128)  g_WTh[j * 256 + e] = __float2half_rn(Wk[(j - 64) * 256 + e]);
    else if (j < 384)  g_WTh[j * 256 + e] = __float2half_rn(Wg[(j - 128) * 256 + e]);
    else if (j < 640)  g_WTh[j * 256 + e] = __float2half_rn(Wo[(j - 384) * 512 + e]);
    else if (j < 896)  g_W2h[(j - 640) * 256 + e] = __float2half_rn(Wo[(j - 640) * 512 + 256 + e]);
    else {
        size_t i = ((size_t)(j - 896) * 256 + e) * 8;
        float4 f0 = *(const float4*)(embs + i);
        float4 f1 = *(const float4*)(embs + i + 4);
        __half2 h[4];
        h[0] = __floats2half2_rn(f0.x, f0.y);
        h[1] = __floats2half2_rn(f0.z, f0.w);
        h[2] = __floats2half2_rn(f1.x, f1.y);
        h[3] = __floats2half2_rn(f1.z, f1.w);
        *(uint4*)(g_embh + i) = *(uint4*)h;
    }
}

// ---------------- GEMM template (fp16 m16n8k16, 2-stage cp.async) ----------
// Tile MROWS x BROWS, NTH threads (8 warps = (MROWS/32) M-groups x rest N).
// MODE 0: A = g_embh (contiguous), B = g_WTh slab (nbase selects slabs)
// MODE 1: A = g_ctxh, B = g_W2h -> + E1c(table), fused LN -> out
template <int MODE, int MROWS, int BROWS, int NTH>
__global__ __launch_bounds__(NTH, 2)
void gemm_kernel(const float* __restrict__ all_embs,
                 const int* __restrict__ center_idx,
                 const float* __restrict__ bg,
                 const float* __restrict__ bo,
                 const float* __restrict__ gamma,
                 const float* __restrict__ beta,
                 float* __restrict__ out,
                 int nbase) {
    constexpr int A_BY = MROWS * RPITCH;
    constexpr int STAGE_BYTES = (MROWS + BROWS) * RPITCH;
    constexpr int MGROUPS = MROWS / 32;
    extern __shared__ char sm[];
    __shared__ int   ridx[MROWS];
    __shared__ float redS[MROWS][4];
    __shared__ float redQ[MROWS][4];

    const int t    = threadIdx.x;
    const int lane = t & 31;
    const int warp = t >> 5;
    const int m0 = blockIdx.x * MROWS;
    const int n0 = (nbase + blockIdx.y) * BROWS;
    const __half* Bmat = (MODE == 0) ? (g_WTh + (size_t)n0 * 256) : g_W2h;

    if (MODE == 1 && t < MROWS) ridx[t] = center_idx[m0 + t];
    __syncthreads();

    const uint32_t sm_u32 = (uint32_t)__cvta_generic_to_shared(sm);
    const int g   = lane >> 2;
    const int tg  = lane & 3;
    const int mb  = (warp % MGROUPS) * 32;
    const int nbo = (warp / MGROUPS) * 64;

    uint32_t a_off[2], b_off[4];
#pragma unroll
    for (int mt = 0; mt < 2; mt++)
        a_off[mt] = (mb + mt * 16 + (lane & 15)) * RPITCH + ((lane >> 4) & 1) * 16;
#pragma unroll
    for (int p = 0; p < 4; p++)
        b_off[p] = A_BY + (nbo + p * 16 + ((lane >> 4) & 1) * 8 + (lane & 7)) * RPITCH
                   + ((lane >> 3) & 1) * 16;

    auto load_stage = [&](int kt, int s) {
        const uint32_t dst0 = sm_u32 + s * STAGE_BYTES;
        const int kk = kt * 64;                      // halfs
        for (int idx = t; idx < MROWS * 8; idx += NTH) {
            int row = idx >> 3, ch = idx & 7;
            const __half* src;
            if (MODE == 0) {
                int r = m0 + row; if (r >= NEMB) r = NEMB - 1;
                src = g_embh + (size_t)r * 256 + kk + ch * 8;
            } else {
                src = g_ctxh + (size_t)(m0 + row) * 256 + kk + ch * 8;
            }
            cp_async16(dst0 + row * RPITCH + ch * 16, src);
        }
        for (int idx = t; idx < BROWS * 8; idx += NTH) {
            int row = idx >> 3, ch = idx & 7;
            cp_async16(dst0 + A_BY + row * RPITCH + ch * 16,
                       Bmat + (size_t)row * 256 + kk + ch * 8);
        }
    };

    float acc[2][8][4] = {};
    uint32_t af[2][2][4];
    uint32_t bf[2][8][2];

    auto load_frags = [&](uint32_t stage, int ks, int buf) {
        const uint32_t kbyte = ks * 32;              // 16 halfs
#pragma unroll
        for (int mt = 0; mt < 2; mt++)
            ldsm_x4(af[buf][mt][0], af[buf][mt][1], af[buf][mt][2], af[buf][mt][3],
                    stage + a_off[mt] + kbyte);
#pragma unroll
        for (int p = 0; p < 4; p++)
            ldsm_x4(bf[buf][2 * p][0], bf[buf][2 * p][1], bf[buf][2 * p + 1][0],
                    bf[buf][2 * p + 1][1], stage + b_off[p] + kbyte);
    };

    load_stage(0, 0);
    asm volatile("cp.async.commit_group;\n" ::: "memory");

#pragma unroll 1
    for (int it = 0; it < 4; ++it) {
        const int s = it & 1;
        asm volatile("cp.async.wait_group 0;\n" ::: "memory");
        __syncthreads();
        if (it + 1 < 4) load_stage(it + 1, s ^ 1);
        asm volatile("cp.async.commit_group;\n" ::: "memory");

        const uint32_t stage = sm_u32 + s * STAGE_BYTES;
        load_frags(stage, 0, 0);
#pragma unroll
        for (int ks = 0; ks < 4; ks++) {
            const int cur = ks & 1;
            if (ks < 3) load_frags(stage, ks + 1, cur ^ 1);
#pragma unroll
            for (int mt = 0; mt < 2; mt++)
#pragma unroll
                for (int nt = 0; nt < 8; nt++)
                    asm volatile(
                        "mma.sync.aligned.m16n8k16.row.col.f32.f16.f16.f32 "
                        "{%0,%1,%2,%3}, {%4,%5,%6,%7}, {%8,%9}, {%0,%1,%2,%3};\n"
                        : "+f"(acc[mt][nt][0]), "+f"(acc[mt][nt][1]),
                          "+f"(acc[mt][nt][2]), "+f"(acc[mt][nt][3])
                        : "r"(af[cur][mt][0]), "r"(af[cur][mt][1]),
                          "r"(af[cur][mt][2]), "r"(af[cur][mt][3]),
                          "r"(bf[cur][nt][0]), "r"(bf[cur][nt][1]));
        }
    }

    if (MODE == 0) {
#pragma unroll
        for (int mt = 0; mt < 2; mt++)
#pragma unroll
            for (int nt = 0; nt < 8; nt++) {
                int j = n0 + nbo + nt * 8 + tg * 2;   // [0,640)
#pragma unroll
                for (int h = 0; h < 2; h++) {
                    int row = m0 + mb + mt * 16 + g + h * 8;
                    if (row >= NEMB) continue;
                    float v0 = acc[mt][nt][h * 2 + 0];
                    float v1 = acc[mt][nt][h * 2 + 1];
                    if (j < 64) {
                        *(__half2*)(g_qh + (size_t)row * 64 + j) = __floats2half2_rn(v0, v1);
                    } else if (j < 128) {
                        *(__half2*)(g_keh + (size_t)row * 64 + (j - 64)) = __floats2half2_rn(v0, v1);
                    } else if (j < 384) {
                        v0 = 1.f / (1.f + __expf(-(v0 + bg[j - 128])));
                        v1 = 1.f / (1.f + __expf(-(v1 + bg[j - 127])));
                        *(__half2*)(g_gateh + (size_t)row * 256 + (j - 128)) = __floats2half2_rn(v0, v1);
                    } else {
                        float2 em = *(const float2*)(all_embs + (size_t)row * 256 + (j - 384));
                        v0 += bo[j - 384] + em.x;
                        v1 += bo[j - 383] + em.y;
                        *(float2*)(g_E1c + (size_t)row * 256 + (j - 384)) = make_float2(v0, v1);
                    }
                }
            }
    } else {
        // MODE 1: + E1c(table), fused LayerNorm (full 256-col rows in-CTA)
        float rs[4] = {0.f, 0.f, 0.f, 0.f};
        float rq[4] = {0.f, 0.f, 0.f, 0.f};
#pragma unroll
        for (int mt = 0; mt < 2; mt++)
#pragma unroll
            for (int h = 0; h < 2; h++) {
                int lr = mb + mt * 16 + g + h * 8;
                const float* e1r = g_E1c + (size_t)ridx[lr] * 256;
                float s = 0.f, q = 0.f;
#pragma unroll
                for (int nt = 0; nt < 8; nt++) {
                    int j = nbo + nt * 8 + tg * 2;
                    float2 e1 = *(const float2*)(e1r + j);
                    float v0 = acc[mt][nt][h * 2 + 0] + e1.x;
                    float v1 = acc[mt][nt][h * 2 + 1] + e1.y;
                    acc[mt][nt][h * 2 + 0] = v0;
                    acc[mt][nt][h * 2 + 1] = v1;
                    s += v0 + v1;
                    q += v0 * v0 + v1 * v1;
                }
                rs[mt * 2 + h] = s;
                rq[mt * 2 + h] = q;
            }
#pragma unroll
        for (int i = 0; i < 4; i++) {
            rs[i] += __shfl_xor_sync(0xffffffffu, rs[i], 1);
            rs[i] += __shfl_xor_sync(0xffffffffu, rs[i], 2);
            rq[i] += __shfl_xor_sync(0xffffffffu, rq[i], 1);
            rq[i] += __shfl_xor_sync(0xffffffffu, rq[i], 2);
        }
        const int nw = warp / MGROUPS;
        if (tg == 0) {
#pragma unroll
            for (int mt = 0; mt < 2; mt++)
#pragma unroll
                for (int h = 0; h < 2; h++) {
                    int lr = mb + mt * 16 + g + h * 8;
                    redS[lr][nw] = rs[mt * 2 + h];
                    redQ[lr][nw] = rq[mt * 2 + h];
                }
        }
        __syncthreads();
        float mu[4], rstd[4];
#pragma unroll
        for (int mt = 0; mt < 2; mt++)
#pragma unroll
            for (int h = 0; h < 2; h++) {
                int lr = mb + mt * 16 + g + h * 8;
                float s = redS[lr][0] + redS[lr][1] + redS[lr][2] + redS[lr][3];
                float q = redQ[lr][0] + redQ[lr][1] + redQ[lr][2] + redQ[lr][3];
                float m = s * (1.f / 256.f);
                float v = q * (1.f / 256.f) - m * m;
                mu[mt * 2 + h] = m;
                rstd[mt * 2 + h] = rsqrtf(v + 1e-5f);
            }
#pragma unroll
        for (int mt = 0; mt < 2; mt++)
#pragma unroll
            for (int nt = 0; nt < 8; nt++) {
                int j = nbo + nt * 8 + tg * 2;
                float2 gm = *(const float2*)(gamma + j);
                float2 bt = *(const float2*)(beta + j);
#pragma unroll
                for (int h = 0; h < 2; h++) {
                    int row = m0 + mb + mt * 16 + g + h * 8;
                    float m = mu[mt * 2 + h], r = rstd[mt * 2 + h];
                    float o0 = (acc[mt][nt][h * 2 + 0] - m) * r * gm.x + bt.x;
                    float o1 = (acc[mt][nt][h * 2 + 1] - m) * r * gm.y + bt.y;
                    *(float2*)(out + (size_t)row * 256 + j) = make_float2(o0, o1);
                }
            }
    }
}

// ---------------- neigh: group-parallel logits + hfma2 streamed context ----
__global__ __launch_bounds__(256)
void neigh_kernel(const int* __restrict__ center_idx,
                  const int* __restrict__ nb_idx,
                  const float* __restrict__ nb_w) {
    const int warp = threadIdx.x >> 5;
    const int lane = threadIdx.x & 31;
    const int b = blockIdx.x * 8 + warp;
    const int grp = lane >> 3;
    const int u   = lane & 7;

    const int cidx = center_idx[b];

    uint4 qv = *(const uint4*)(g_qh + (size_t)cidx * 64 + u * 8);
    const __half2* qh = (const __half2*)&qv;
    float2 qf[4];
#pragma unroll
    for (int i = 0; i < 4; i++) qf[i] = __half22float2(qh[i]);

    int   myidx = 0;
    float myw   = 0.f;
    if (lane < 16) {
        myidx = nb_idx[b * 16 + lane];
        myw   = fmaxf(nb_w[b * 16 + lane], 1e-6f);
    }

    float v[4];
#pragma unroll
    for (int p = 0; p < 4; p++) {
        int r = __shfl_sync(0xffffffffu, myidx, p * 4 + grp);
        uint4 kv = *(const uint4*)(g_keh + (size_t)r * 64 + u * 8);
        const __half2* kh = (const __half2*)&kv;
        float s = 0.f;
#pragma unroll
        for (int i = 0; i < 4; i++) {
            float2 kf = __half22float2(kh[i]);
            s = fmaf(kf.x, qf[i].x, s);
            s = fmaf(kf.y, qf[i].y, s);
        }
        s += __shfl_xor_sync(0xffffffffu, s, 1);
        s += __shfl_xor_sync(0xffffffffu, s, 2);
        s += __shfl_xor_sync(0xffffffffu, s, 4);
        v[p] = s;
    }
    const int src = (lane & 3) * 8;
    float t0 = __shfl_sync(0xffffffffu, v[0], src);
    float t1 = __shfl_sync(0xffffffffu, v[1], src);
    float t2 = __shfl_sync(0xffffffffu, v[2], src);
    float t3 = __shfl_sync(0xffffffffu, v[3], src);
    const int sel = lane >> 2;
    float lgj = (sel == 0) ? t0 : (sel == 1) ? t1 : (sel == 2) ? t2 : t3;

    float l = (lane < 16) ? lgj * 0.125f : -1e30f;
    float mx = l;
#pragma unroll
    for (int off = 8; off >= 1; off >>= 1)
        mx = fmaxf(mx, __shfl_xor_sync(0xffffffffu, mx, off));
    float e = (lane < 16) ? myw * __expf(l - mx) : 0.f;
    float es = e;
#pragma unroll
    for (int off = 8; off >= 1; off >>= 1)
        es += __shfl_xor_sync(0xffffffffu, es, off);
    float ai = e / es;

    __half2 ai2 = __floats2half2_rn(ai, ai);
    uint32_t aiu = *(uint32_t*)&ai2;
    __half2 hacc[2][4];
#pragma unroll
    for (int s2 = 0; s2 < 2; s2++)
#pragma unroll
        for (int i = 0; i < 4; i++) hacc[s2][i] = __floats2half2_rn(0.f, 0.f);

#pragma unroll
    for (int k = 0; k < 16; k++) {
        int      r   = __shfl_sync(0xffffffffu, myidx, k);
        uint32_t aku = __shfl_sync(0xffffffffu, aiu, k);
        __half2  akh = *(__half2*)&aku;
        uint4 nv = *(const uint4*)(g_embh + (size_t)r * 256 + lane * 8);
        const __half2* hp = (const __half2*)&nv;
        const int s2 = k & 1;
#pragma unroll
        for (int i = 0; i < 4; i++)
            hacc[s2][i] = __hfma2(hp[i], akh, hacc[s2][i]);
    }

    float a[8];
#pragma unroll
    for (int i = 0; i < 4; i++) {
        float2 f0 = __half22float2(hacc[0][i]);
        float2 f1 = __half22float2(hacc[1][i]);
        a[2 * i + 0] = f0.x + f1.x;
        a[2 * i + 1] = f0.y + f1.y;
    }

    uint4 gv = *(const uint4*)(g_gateh + (size_t)cidx * 256 + lane * 8);
    const __half2* gh = (const __half2*)&gv;
    __half2 hout[4];
#pragma unroll
    for (int i = 0; i < 4; i++) {
        float2 gf = __half22float2(gh[i]);
        hout[i] = __floats2half2_rn(gf.x * a[2 * i + 0], gf.y * a[2 * i + 1]);
    }
    *(uint4*)(g_ctxh + (size_t)b * 256 + lane * 8) = *(uint4*)hout;
}

// ---------------- launch ---------------------------------------------------
extern "C" void kernel_launch(void* const* d_in, const int* in_sizes, int n_in,
                              void* d_out, int out_size) {
    const float* all_embs   = (const float*)d_in[0];
    const int*   center_idx = (const int*)d_in[1];
    const int*   nb_idx     = (const int*)d_in[2];
    const float* nb_w       = (const float*)d_in[3];
    const float* Wq         = (const float*)d_in[4];
    const float* Wk         = (const float*)d_in[5];
    const float* Wg         = (const float*)d_in[6];
    const float* bg         = (const float*)d_in[7];
    const float* Wo         = (const float*)d_in[8];
    const float* bo         = (const float*)d_in[9];
    const float* gamma      = (const float*)d_in[10];
    const float* beta       = (const float*)d_in[11];
    float* out = (float*)d_out;

    const int sm0 = 2 * (128 + 128) * RPITCH;   // 73728
    const int sm1 = 2 * (64 + 256) * RPITCH;    // 92160

    static cudaStream_t s2 = nullptr;
    static cudaEvent_t ev1 = nullptr, ev2 = nullptr;
    static int configured = 0;
    if (!configured) {
        cudaFuncSetAttribute((const void*)gemm_kernel<0, 128, 128, 256>,
                             cudaFuncAttributeMaxDynamicSharedMemorySize, sm0);
        cudaFuncSetAttribute((const void*)gemm_kernel<1, 64, 256, 256>,
                             cudaFuncAttributeMaxDynamicSharedMemorySize, sm1);
        cudaStreamCreateWithFlags(&s2, cudaStreamNonBlocking);
        cudaEventCreateWithFlags(&ev1, cudaEventDisableTiming);
        cudaEventCreateWithFlags(&ev2, cudaEventDisableTiming);
        configured = 1;
    }

    // main: prep -> gemm0a(q/ke/gate) -> neigh -> [join] -> gemm1
    // side: [fork after prep] gemm0b(E1c slabs) -> [join]
    prep_kernel<<<896 + 2500, 256>>>(Wq, Wk, Wg, Wo, all_embs);
    cudaEventRecord(ev1, 0);
    cudaStreamWaitEvent(s2, ev1, 0);

    gemm_kernel<0, 128, 128, 256><<<dim3((NEMB + 127) / 128, 3), 256, sm0>>>(
        all_embs, center_idx, bg, bo, gamma, beta, nullptr, 0);      // q|ke|gate slabs
    gemm_kernel<0, 128, 128, 256><<<dim3((NEMB + 127) / 128, 2), 256, sm0, s2>>>(
        all_embs, center_idx, bg, bo, gamma, beta, nullptr, 3);      // E1c slabs (overlapped)

    neigh_kernel<<<BATCH / 8, 256>>>(center_idx, nb_idx, nb_w);

    cudaEventRecord(ev2, s2);
    cudaStreamWaitEvent(0, ev2, 0);
    gemm_kernel<1, 64, 256, 256><<<dim3(BATCH / 64, 1), 256, sm1>>>(
        all_embs, center_idx, bg, bo, gamma, beta, out, 0);          // out + LN (2 CTA/SM)
}